// round 9
// baseline (speedup 1.0000x reference)
#include <cuda_runtime.h>
#include <cuda_fp16.h>
#include <cstdint>

#define BATCH 8
#define CH    64
#define NPIX  4096

__device__ __align__(128) __half g_fq[BATCH*NPIX*CH]; // f*log2e [b][n][c]
__device__ __align__(128) __half g_gq[BATCH*NPIX*CH]; // g       [b][n][c]
__device__ __align__(128) __half g_hq[BATCH*CH*NPIX]; // h       [b][c][n]
__device__ float g_L[BATCH*NPIX];
__device__ __align__(128) uint8_t g_Wq[24576];
__device__ __align__(128) float   g_bias[192];

__device__ __forceinline__ uint32_t smem_u32(const void* p){
    uint32_t a; asm("{ .reg .u64 t; cvta.to.shared.u64 t, %1; cvt.u32.u64 %0, t; }":"=r"(a):"l"(p)); return a;
}
__device__ __forceinline__ uint32_t swz(uint32_t o){ return o ^ ((o>>3)&0x70); }
__device__ __forceinline__ uint32_t swzH(uint32_t o){ return o ^ ((o>>4)&0x70); }
__device__ __forceinline__ float ex2(float x){
    float y; asm("ex2.approx.f32 %0, %1;":"=f"(y):"f"(x)); return y;
}
__device__ __forceinline__ float lg2(float x){
    float y; asm("lg2.approx.f32 %0, %1;":"=f"(y):"f"(x)); return y;
}
__device__ __forceinline__ uint32_t cvtpack(float lo, float hi){
    uint32_t r; asm("cvt.rn.f16x2.f32 %0, %1, %2;" : "=r"(r) : "f"(hi), "f"(lo)); return r;
}
__device__ __forceinline__ uint32_t sub2(uint32_t a, uint32_t b){
    uint32_t r; asm("sub.rn.f16x2 %0, %1, %2;" : "=r"(r) : "r"(a), "r"(b)); return r;
}
__device__ __forceinline__ uint32_t ex2h2(uint32_t a){
    uint32_t r; asm("ex2.approx.f16x2 %0, %1;" : "=r"(r) : "r"(a)); return r;
}
#define CP16(dst, src) asm volatile("cp.async.cg.shared.global [%0], [%1], 16;"::"r"(dst),"l"(src):"memory")
#define CPCOMMIT()     asm volatile("cp.async.commit_group;":::"memory")
#define CPWAIT(n)      asm volatile("cp.async.wait_group %0;"::"n"(n):"memory")

__device__ __forceinline__ void ldsm4(uint32_t r[4], uint32_t addr){
    asm volatile("ldmatrix.sync.aligned.m8n8.x4.shared.b16 {%0,%1,%2,%3},[%4];"
        : "=r"(r[0]),"=r"(r[1]),"=r"(r[2]),"=r"(r[3]) : "r"(addr));
}
__device__ __forceinline__ void ldsm4t(uint32_t r[4], uint32_t addr){
    asm volatile("ldmatrix.sync.aligned.m8n8.x4.trans.shared.b16 {%0,%1,%2,%3},[%4];"
        : "=r"(r[0]),"=r"(r[1]),"=r"(r[2]),"=r"(r[3]) : "r"(addr));
}
__device__ __forceinline__ void mma_f16(float d[4], const uint32_t a[4], const uint32_t b[2]){
    asm volatile("mma.sync.aligned.m16n8k16.row.col.f32.f16.f16.f32 "
        "{%0,%1,%2,%3},{%4,%5,%6,%7},{%8,%9},{%0,%1,%2,%3};"
        : "+f"(d[0]),"+f"(d[1]),"+f"(d[2]),"+f"(d[3])
        : "r"(a[0]),"r"(a[1]),"r"(a[2]),"r"(a[3]),"r"(b[0]),"r"(b[1]));
}
__device__ __forceinline__ void mma_h16(uint32_t d[2], const uint32_t a[4], const uint32_t b[2]){
    asm volatile("mma.sync.aligned.m16n8k16.row.col.f16.f16.f16.f16 "
        "{%0,%1},{%2,%3,%4,%5},{%6,%7},{%0,%1};"
        : "+r"(d[0]),"+r"(d[1])
        : "r"(a[0]),"r"(a[1]),"r"(a[2]),"r"(a[3]),"r"(b[0]),"r"(b[1]));
}

// ---------------- Stage 0: W/bias prep ---------------------------------------
__global__ __launch_bounds__(256) void prep_w(
    const float* __restrict__ Wf, const float* __restrict__ bf,
    const float* __restrict__ Wg, const float* __restrict__ bg,
    const float* __restrict__ Wh, const float* __restrict__ bh)
{
    const int t = threadIdx.x;
    for (int q = t; q < 3*4096; q += 256) {
        int mtx = q >> 12, idx = q & 4095;
        const float* Wsrc = (mtx==0)?Wf:((mtx==1)?Wg:Wh);
        float v = Wsrc[idx] * ((mtx==0) ? 1.44269504f : 1.0f);
        int o = idx >> 6, k = idx & 63;
        *(__half*)(g_Wq + mtx*8192u + swz(o*128 + k*2)) = __float2half_rn(v);
    }
    if (t < 192) {
        const float* bsrc = (t<64)?bf:((t<128)?bg:bh);
        g_bias[t] = bsrc[t&63] * ((t<64) ? 1.44269504f : 1.0f);
    }
}

// ---------------- Stage A: projections via HMMA ------------------------------
__global__ __launch_bounds__(256,2) void fgh_hmma(const float* __restrict__ x)
{
    extern __shared__ uint8_t dyn0[];
    uint8_t* A = (uint8_t*)(((uintptr_t)dyn0 + 1023) & ~(uintptr_t)1023);
    const uint32_t Au = smem_u32(A);
    const uint32_t BIAS=24576, SX=25600, STG=41984;

    const int t = threadIdx.x, lane = t&31, wid = t>>5;
    const int b = blockIdx.y, n0 = blockIdx.x*128;

    for (int q = t; q < 1536; q += 256) CP16(Au + q*16, (const char*)g_Wq + q*16);
    if (t < 48) CP16(Au + BIAS + t*16, (const char*)g_bias + t*16);
    CPCOMMIT();

    {
        int c = t>>2, nb0 = (t&3)*32;
        const float* xr = x + ((size_t)b*CH + c)*NPIX + n0 + nb0;
        for (int u = 0; u < 16; u++) {
            float2 v = *(const float2*)(xr + 2*u);
            *(uint32_t*)(A + SX + swzH((uint32_t)(c*256 + (nb0+2*u)*2))) = cvtpack(v.x, v.y);
        }
    }
    CPWAIT(0); __syncthreads();

    uint32_t ax[4][4];
    const int m0 = wid*16;
#pragma unroll
    for (int kk = 0; kk < 4; kk++) {
        int row = kk*16 + (lane&7) + ((lane>>4)<<3);
        int col = m0 + ((lane>>3)&1)*8;
        ldsm4t(ax[kk], Au + SX + swzH((uint32_t)(row*256 + col*2)));
    }
    const float* bias = (const float*)(A+BIAS);

#pragma unroll 1
    for (int mtx = 0; mtx < 3; mtx++) {
        float acc[8][4];
#pragma unroll
        for (int ob = 0; ob < 8; ob++) {
            float b0 = bias[mtx*64 + ob*8 + (lane&3)*2];
            float b1 = bias[mtx*64 + ob*8 + (lane&3)*2 + 1];
            acc[ob][0]=b0; acc[ob][1]=b1; acc[ob][2]=b0; acc[ob][3]=b1;
        }
#pragma unroll
        for (int kk = 0; kk < 4; kk++) {
#pragma unroll
            for (int op = 0; op < 4; op++) {
                uint32_t off = swz((uint32_t)((op*16 + ((lane>>4)&1)*8 + (lane&7))*128
                                              + kk*32 + ((lane>>3)&1)*16));
                uint32_t bw[4];
                ldsm4(bw, Au + mtx*8192u + off);
                mma_f16(acc[2*op],   ax[kk], &bw[0]);
                mma_f16(acc[2*op+1], ax[kk], &bw[2]);
            }
        }
        __syncthreads();
#pragma unroll
        for (int ob = 0; ob < 8; ob++) {
            int o = ob*8 + (lane&3)*2, r = lane>>2;
            *(uint32_t*)(A + STG + swz((uint32_t)((m0+r)*128   + o*2))) = cvtpack(acc[ob][0], acc[ob][1]);
            *(uint32_t*)(A + STG + swz((uint32_t)((m0+r+8)*128 + o*2))) = cvtpack(acc[ob][2], acc[ob][3]);
        }
        __syncthreads();
        if (mtx < 2) {
            __half* dst = ((mtx==0)?g_fq:g_gq) + ((size_t)b*NPIX + n0)*CH;
            int n = t>>1, half = t&1;
#pragma unroll
            for (int q16 = 0; q16 < 4; q16++) {
                int4 v = *(int4*)(A + STG + swz((uint32_t)(n*128 + half*64 + q16*16)));
                *(int4*)((char*)(dst + (size_t)n*CH + half*32) + q16*16) = v;
            }
        } else {
            int c = t>>2, sg = t&3;
            __half* dst = g_hq + ((size_t)b*CH + c)*NPIX + n0 + sg*32;
#pragma unroll
            for (int u = 0; u < 16; u++) {
                int n = sg*32 + 2*u;
                uint32_t e0 = *(uint16_t*)(A + STG + swz((uint32_t)(n*128 + c*2)));
                uint32_t e1 = *(uint16_t*)(A + STG + swz((uint32_t)((n+1)*128 + c*2)));
                *(uint32_t*)(dst + 2*u) = e0 | (e1<<16);
            }
        }
    }
}

// ---------------- Pass 1: L[i]; M=32/warp, i-tile 256 ------------------------
// grid (16, 8), 256 threads. smem: F 32K | G dbl 2x16K = 64K.
__global__ __launch_bounds__(256,1) void pass1_hmma()
{
    extern __shared__ uint8_t dyn1[];
    uint8_t* A = (uint8_t*)(((uintptr_t)dyn1 + 1023) & ~(uintptr_t)1023);
    const uint32_t Au = smem_u32(A);
    const uint32_t FQ=0, GB=32768;

    const int t = threadIdx.x, lane = t&31, wid = t>>5;
    const int b = blockIdx.y, i0 = blockIdx.x*256;

    {
        const char* fq = (const char*)(g_fq + ((size_t)b*NPIX+i0)*CH);
        for (int q = t; q < 2048; q += 256) CP16(Au+FQ+swz(q*16), fq + q*16);
        CPCOMMIT();
    }
#pragma unroll 1
    for (int pre = 0; pre < 2; pre++) {
        const char* gq = (const char*)(g_gq + ((size_t)b*NPIX + pre*128)*CH);
        uint32_t base = Au + GB + pre*16384;
        for (int q = t; q < 1024; q += 256) CP16(base+swz(q*16), gq + q*16);
        CPCOMMIT();
    }
    CPWAIT(2); __syncthreads();

    uint32_t af[2][4][4];
#pragma unroll
    for (int s = 0; s < 2; s++)
#pragma unroll
    for (int kk = 0; kk < 4; kk++) {
        uint32_t off = swz((uint32_t)((wid*32 + s*16 + (lane&15))*128 + kk*32 + ((lane>>4)&1)*16));
        ldsm4(af[s][kk], Au+FQ+off);
    }

    float z[2][2] = {{0.f,0.f},{0.f,0.f}};

#pragma unroll 1
    for (int jt = 0; jt < 32; jt++) {
        CPWAIT(1); __syncthreads();
        uint32_t gb = Au + GB + (uint32_t)(jt&1)*16384;

        uint32_t sacc[2][16][2];
#pragma unroll
        for (int s = 0; s < 2; s++)
#pragma unroll
        for (int nb = 0; nb < 16; nb++) { sacc[s][nb][0]=0u; sacc[s][nb][1]=0u; }

#pragma unroll
        for (int kk = 0; kk < 4; kk++) {
#pragma unroll
            for (int p = 0; p < 8; p++) {
                uint32_t off = swz((uint32_t)((p*16 + ((lane>>4)&1)*8 + (lane&7))*128
                                              + kk*32 + ((lane>>3)&1)*16));
                uint32_t bh[4];
                ldsm4(bh, gb+off);
                mma_h16(sacc[0][2*p],   af[0][kk], &bh[0]);
                mma_h16(sacc[0][2*p+1], af[0][kk], &bh[2]);
                mma_h16(sacc[1][2*p],   af[1][kk], &bh[0]);
                mma_h16(sacc[1][2*p+1], af[1][kk], &bh[2]);
            }
        }
#pragma unroll
        for (int s = 0; s < 2; s++)
#pragma unroll
        for (int nb = 0; nb < 16; nb++) {
            float2 a = __half22float2(*(const __half2*)&sacc[s][nb][0]);
            float2 c = __half22float2(*(const __half2*)&sacc[s][nb][1]);
            z[s][0] += ex2(a.x) + ex2(a.y);
            z[s][1] += ex2(c.x) + ex2(c.y);
        }

        __syncthreads();
        if (jt+2 < 32) {
            const char* gq = (const char*)(g_gq + ((size_t)b*NPIX + (jt+2)*128)*CH);
            uint32_t base = Au + GB + (uint32_t)(jt&1)*16384;
            for (int q = t; q < 1024; q += 256) CP16(base+swz(q*16), gq + q*16);
        }
        CPCOMMIT();
    }

#pragma unroll
    for (int s = 0; s < 2; s++) {
        float z0 = z[s][0], z1 = z[s][1];
        z0 += __shfl_xor_sync(0xFFFFFFFFu, z0, 1);
        z0 += __shfl_xor_sync(0xFFFFFFFFu, z0, 2);
        z1 += __shfl_xor_sync(0xFFFFFFFFu, z1, 1);
        z1 += __shfl_xor_sync(0xFFFFFFFFu, z1, 2);
        if ((lane&3) == 0) {
            int r = b*NPIX + i0 + wid*32 + s*16 + (lane>>2);
            g_L[r]   = lg2(z0);
            g_L[r+8] = lg2(z1);
        }
    }
}

// ---------------- Pass 2: out'[j,c]; M=32/warp, j-tile 256 --------------------
// grid (16, 8), 256 threads. smem: G 32K + 2 x (f 8K + h 8K + L 256B).
#define BUFST 16640u
#define B0    32768u
#define OF_FQ 0u
#define OF_HH 8192u
#define OF_L  16384u
__global__ __launch_bounds__(256,1) void pass2_hmma(
    const float* __restrict__ x, const float* __restrict__ gamma,
    float* __restrict__ out)
{
    extern __shared__ uint8_t dyn2[];
    uint8_t* A = (uint8_t*)(((uintptr_t)dyn2 + 1023) & ~(uintptr_t)1023);
    const uint32_t Au = smem_u32(A);

    const int t = threadIdx.x, lane = t&31, wid = t>>5;
    const int b = blockIdx.y, j0 = blockIdx.x*256;

    {
        const char* gq = (const char*)(g_gq + ((size_t)b*NPIX+j0)*CH);
        for (int q = t; q < 2048; q += 256) CP16(Au+swz(q*16), gq + q*16);
        CPCOMMIT();
    }
#pragma unroll 1
    for (int pre = 0; pre < 2; pre++) {
        const int i0 = pre*64;
        uint32_t base = Au + B0 + pre*BUFST;
        const char* fq = (const char*)(g_fq + ((size_t)b*NPIX+i0)*CH);
        for (int q = t; q < 512; q += 256) CP16(base+OF_FQ+swz(q*16), fq + q*16);
        const char* hq = (const char*)(g_hq + (size_t)b*CH*NPIX + i0);
        for (int q = t; q < 512; q += 256)
            CP16(base+OF_HH+swz(q*16), hq + (uint32_t)(q>>3)*NPIX*2 + (uint32_t)(q&7)*16);
        if (t < 16) CP16(base+OF_L + t*16, (const char*)(g_L + b*NPIX + i0) + t*16);
        CPCOMMIT();
    }
    CPWAIT(2); __syncthreads();

    uint32_t ag[2][4][4];
#pragma unroll
    for (int s = 0; s < 2; s++)
#pragma unroll
    for (int kk = 0; kk < 4; kk++) {
        uint32_t off = swz((uint32_t)((wid*32 + s*16 + (lane&15))*128 + kk*32 + ((lane>>4)&1)*16));
        ldsm4(ag[s][kk], Au+off);
    }

    float oacc[2][8][4];
#pragma unroll
    for (int s = 0; s < 2; s++)
#pragma unroll
    for (int nb = 0; nb < 8; nb++) { oacc[s][nb][0]=0.f; oacc[s][nb][1]=0.f; oacc[s][nb][2]=0.f; oacc[s][nb][3]=0.f; }

#pragma unroll 1
    for (int it = 0; it < 64; it++) {
        CPWAIT(1); __syncthreads();
        uint32_t bb = Au + B0 + (uint32_t)(it&1)*BUFST;
        const float* Lf = (const float*)(A + B0 + (it&1)*BUFST + OF_L);

        uint32_t L2[8];
#pragma unroll
        for (int nb = 0; nb < 8; nb++) {
            int ic = nb*8 + (lane&3)*2;
            L2[nb] = cvtpack(Lf[ic], Lf[ic+1]);
        }

        uint32_t sacc[2][8][2];
#pragma unroll
        for (int s = 0; s < 2; s++)
#pragma unroll
        for (int nb = 0; nb < 8; nb++) { sacc[s][nb][0]=0u; sacc[s][nb][1]=0u; }
#pragma unroll
        for (int kk = 0; kk < 4; kk++) {
#pragma unroll
            for (int p = 0; p < 4; p++) {
                uint32_t off = swz((uint32_t)((p*16 + ((lane>>4)&1)*8 + (lane&7))*128
                                              + kk*32 + ((lane>>3)&1)*16));
                uint32_t bh[4];
                ldsm4(bh, bb+OF_FQ+off);
                mma_h16(sacc[0][2*p],   ag[0][kk], &bh[0]);
                mma_h16(sacc[0][2*p+1], ag[0][kk], &bh[2]);
                mma_h16(sacc[1][2*p],   ag[1][kk], &bh[0]);
                mma_h16(sacc[1][2*p+1], ag[1][kk], &bh[2]);
            }
        }

#pragma unroll
        for (int kk2 = 0; kk2 < 4; kk2++) {
            int nb0 = 2*kk2, nb1 = nb0+1;
            uint32_t aH0[4], aH1[4];
            aH0[0] = ex2h2(sub2(sacc[0][nb0][0], L2[nb0]));
            aH0[1] = ex2h2(sub2(sacc[0][nb0][1], L2[nb0]));
            aH0[2] = ex2h2(sub2(sacc[0][nb1][0], L2[nb1]));
            aH0[3] = ex2h2(sub2(sacc[0][nb1][1], L2[nb1]));
            aH1[0] = ex2h2(sub2(sacc[1][nb0][0], L2[nb0]));
            aH1[1] = ex2h2(sub2(sacc[1][nb0][1], L2[nb0]));
            aH1[2] = ex2h2(sub2(sacc[1][nb1][0], L2[nb1]));
            aH1[3] = ex2h2(sub2(sacc[1][nb1][1], L2[nb1]));
#pragma unroll
            for (int p = 0; p < 4; p++) {
                uint32_t off = swz((uint32_t)((p*16 + ((lane>>4)&1)*8 + (lane&7))*128
                                              + kk2*32 + ((lane>>3)&1)*16));
                uint32_t bh[4];
                ldsm4(bh, bb+OF_HH+off);
                mma_f16(oacc[0][2*p],   aH0, &bh[0]);
                mma_f16(oacc[0][2*p+1], aH0, &bh[2]);
                mma_f16(oacc[1][2*p],   aH1, &bh[0]);
                mma_f16(oacc[1][2*p+1], aH1, &bh[2]);
            }
        }

        __syncthreads();
        if (it+2 < 64) {
            const int i0 = (it+2)*64;
            uint32_t base = Au + B0 + (uint32_t)(it&1)*BUFST;
            const char* fq = (const char*)(g_fq + ((size_t)b*NPIX+i0)*CH);
            for (int q = t; q < 512; q += 256) CP16(base+OF_FQ+swz(q*16), fq + q*16);
            const char* hq = (const char*)(g_hq + (size_t)b*CH*NPIX + i0);
            for (int q = t; q < 512; q += 256)
                CP16(base+OF_HH+swz(q*16), hq + (uint32_t)(q>>3)*NPIX*2 + (uint32_t)(q&7)*16);
            if (t < 16) CP16(base+OF_L + t*16, (const char*)(g_L + b*NPIX + i0) + t*16);
        }
        CPCOMMIT();
    }

    // Epilogue: stage [64 c][256 j] fp32 (reuses whole smem), coalesced out
    CPWAIT(0); __syncthreads();
    float* outs = (float*)A;
#pragma unroll
    for (int s = 0; s < 2; s++) {
        const int jl = wid*32 + s*16 + (lane>>2);
#pragma unroll
        for (int nb = 0; nb < 8; nb++) {
            int c0 = nb*8 + (lane&3)*2;
            outs[c0*256 + jl]         = oacc[s][nb][0];
            outs[(c0+1)*256 + jl]     = oacc[s][nb][1];
            outs[c0*256 + jl + 8]     = oacc[s][nb][2];
            outs[(c0+1)*256 + jl + 8] = oacc[s][nb][3];
        }
    }
    __syncthreads();
    const float gam = *gamma;
    {
        const int row = t>>2, seg = t&3;   // row = channel, seg covers 64 j
        const float* xr   = x   + ((size_t)b*CH + row)*NPIX + j0 + seg*64;
        float*       orow = out + ((size_t)b*CH + row)*NPIX + j0 + seg*64;
        const float4* sr = (const float4*)(outs + row*256 + seg*64);
#pragma unroll
        for (int u = 0; u < 16; u++) {
            float4 v = sr[u];
            float4 xv = *(const float4*)(xr + u*4);
            float4 r;
            r.x = gam*v.x + xv.x; r.y = gam*v.y + xv.y;
            r.z = gam*v.z + xv.z; r.w = gam*v.w + xv.w;
            *(float4*)(orow + u*4) = r;
        }
    }
}

// -----------------------------------------------------------------------------
extern "C" void kernel_launch(void* const* d_in, const int* in_sizes, int n_in,
                              void* d_out, int out_size)
{
    const float* x     = (const float*)d_in[0];
    const float* Wf    = (const float*)d_in[1];
    const float* bf    = (const float*)d_in[2];
    const float* Wg    = (const float*)d_in[3];
    const float* bg    = (const float*)d_in[4];
    const float* Wh    = (const float*)d_in[5];
    const float* bh    = (const float*)d_in[6];
    const float* gamma = (const float*)d_in[7];
    float* out = (float*)d_out;
    (void)in_sizes; (void)n_in; (void)out_size;

    cudaFuncSetAttribute(fgh_hmma,   cudaFuncAttributeMaxDynamicSharedMemorySize, 58368+1024);
    cudaFuncSetAttribute(pass1_hmma, cudaFuncAttributeMaxDynamicSharedMemorySize, 65536+1024);
    cudaFuncSetAttribute(pass2_hmma, cudaFuncAttributeMaxDynamicSharedMemorySize, 66048+1024);

    prep_w<<<1, 256>>>(Wf, bf, Wg, bg, Wh, bh);
    fgh_hmma<<<dim3(32, BATCH), 256, 58368+1024>>>(x);
    pass1_hmma<<<dim3(16, BATCH), 256, 65536+1024>>>();
    pass2_hmma<<<dim3(16, BATCH), 256, 66048+1024>>>(x, gamma, out);
}

// round 10
// speedup vs baseline: 1.0700x; 1.0700x over previous
#include <cuda_runtime.h>
#include <cuda_fp16.h>
#include <cstdint>

#define BATCH 8
#define CH    64
#define NPIX  4096

__device__ __align__(128) __half g_fq[BATCH*NPIX*CH]; // f*log2e [b][n][c]
__device__ __align__(128) __half g_gq[BATCH*NPIX*CH]; // g       [b][n][c]
__device__ __align__(128) __half g_hq[BATCH*CH*NPIX]; // h       [b][c][n]
__device__ float g_L[BATCH*NPIX];
__device__ __align__(128) uint8_t g_Wq[24576];
__device__ __align__(128) float   g_bias[192];

__device__ __forceinline__ uint32_t smem_u32(const void* p){
    uint32_t a; asm("{ .reg .u64 t; cvta.to.shared.u64 t, %1; cvt.u32.u64 %0, t; }":"=r"(a):"l"(p)); return a;
}
__device__ __forceinline__ uint32_t swz(uint32_t o){ return o ^ ((o>>3)&0x70); }
__device__ __forceinline__ uint32_t swzH(uint32_t o){ return o ^ ((o>>4)&0x70); }
__device__ __forceinline__ float ex2(float x){
    float y; asm("ex2.approx.f32 %0, %1;":"=f"(y):"f"(x)); return y;
}
__device__ __forceinline__ float lg2(float x){
    float y; asm("lg2.approx.f32 %0, %1;":"=f"(y):"f"(x)); return y;
}
__device__ __forceinline__ uint32_t cvtpack(float lo, float hi){
    uint32_t r; asm("cvt.rn.f16x2.f32 %0, %1, %2;" : "=r"(r) : "f"(hi), "f"(lo)); return r;
}
__device__ __forceinline__ uint32_t sub2(uint32_t a, uint32_t b){
    uint32_t r; asm("sub.rn.f16x2 %0, %1, %2;" : "=r"(r) : "r"(a), "r"(b)); return r;
}
__device__ __forceinline__ uint32_t ex2h2(uint32_t a){
    uint32_t r; asm("ex2.approx.f16x2 %0, %1;" : "=r"(r) : "r"(a)); return r;
}
#define CP16(dst, src) asm volatile("cp.async.cg.shared.global [%0], [%1], 16;"::"r"(dst),"l"(src):"memory")
#define CPCOMMIT()     asm volatile("cp.async.commit_group;":::"memory")
#define CPWAIT(n)      asm volatile("cp.async.wait_group %0;"::"n"(n):"memory")

__device__ __forceinline__ void ldsm4(uint32_t r[4], uint32_t addr){
    asm volatile("ldmatrix.sync.aligned.m8n8.x4.shared.b16 {%0,%1,%2,%3},[%4];"
        : "=r"(r[0]),"=r"(r[1]),"=r"(r[2]),"=r"(r[3]) : "r"(addr));
}
__device__ __forceinline__ void ldsm4t(uint32_t r[4], uint32_t addr){
    asm volatile("ldmatrix.sync.aligned.m8n8.x4.trans.shared.b16 {%0,%1,%2,%3},[%4];"
        : "=r"(r[0]),"=r"(r[1]),"=r"(r[2]),"=r"(r[3]) : "r"(addr));
}
__device__ __forceinline__ void mma_f16(float d[4], const uint32_t a[4], const uint32_t b[2]){
    asm volatile("mma.sync.aligned.m16n8k16.row.col.f32.f16.f16.f32 "
        "{%0,%1,%2,%3},{%4,%5,%6,%7},{%8,%9},{%0,%1,%2,%3};"
        : "+f"(d[0]),"+f"(d[1]),"+f"(d[2]),"+f"(d[3])
        : "r"(a[0]),"r"(a[1]),"r"(a[2]),"r"(a[3]),"r"(b[0]),"r"(b[1]));
}
__device__ __forceinline__ void mma_h16(uint32_t d[2], const uint32_t a[4], const uint32_t b[2]){
    asm volatile("mma.sync.aligned.m16n8k16.row.col.f16.f16.f16.f16 "
        "{%0,%1},{%2,%3,%4,%5},{%6,%7},{%0,%1};"
        : "+r"(d[0]),"+r"(d[1])
        : "r"(a[0]),"r"(a[1]),"r"(a[2]),"r"(a[3]),"r"(b[0]),"r"(b[1]));
}

// ---------------- Stage 0: W/bias prep ---------------------------------------
__global__ __launch_bounds__(256) void prep_w(
    const float* __restrict__ Wf, const float* __restrict__ bf,
    const float* __restrict__ Wg, const float* __restrict__ bg,
    const float* __restrict__ Wh, const float* __restrict__ bh)
{
    const int t = threadIdx.x;
    for (int q = t; q < 3*4096; q += 256) {
        int mtx = q >> 12, idx = q & 4095;
        const float* Wsrc = (mtx==0)?Wf:((mtx==1)?Wg:Wh);
        float v = Wsrc[idx] * ((mtx==0) ? 1.44269504f : 1.0f);
        int o = idx >> 6, k = idx & 63;
        *(__half*)(g_Wq + mtx*8192u + swz(o*128 + k*2)) = __float2half_rn(v);
    }
    if (t < 192) {
        const float* bsrc = (t<64)?bf:((t<128)?bg:bh);
        g_bias[t] = bsrc[t&63] * ((t<64) ? 1.44269504f : 1.0f);
    }
}

// ---------------- Stage A: projections via HMMA ------------------------------
__global__ __launch_bounds__(256,2) void fgh_hmma(const float* __restrict__ x)
{
    extern __shared__ uint8_t dyn0[];
    uint8_t* A = (uint8_t*)(((uintptr_t)dyn0 + 1023) & ~(uintptr_t)1023);
    const uint32_t Au = smem_u32(A);
    const uint32_t BIAS=24576, SX=25600, STG=41984;

    const int t = threadIdx.x, lane = t&31, wid = t>>5;
    const int b = blockIdx.y, n0 = blockIdx.x*128;

    for (int q = t; q < 1536; q += 256) CP16(Au + q*16, (const char*)g_Wq + q*16);
    if (t < 48) CP16(Au + BIAS + t*16, (const char*)g_bias + t*16);
    CPCOMMIT();

    {
        int c = t>>2, nb0 = (t&3)*32;
        const float* xr = x + ((size_t)b*CH + c)*NPIX + n0 + nb0;
        for (int u = 0; u < 16; u++) {
            float2 v = *(const float2*)(xr + 2*u);
            *(uint32_t*)(A + SX + swzH((uint32_t)(c*256 + (nb0+2*u)*2))) = cvtpack(v.x, v.y);
        }
    }
    CPWAIT(0); __syncthreads();

    uint32_t ax[4][4];
    const int m0 = wid*16;
#pragma unroll
    for (int kk = 0; kk < 4; kk++) {
        int row = kk*16 + (lane&7) + ((lane>>4)<<3);
        int col = m0 + ((lane>>3)&1)*8;
        ldsm4t(ax[kk], Au + SX + swzH((uint32_t)(row*256 + col*2)));
    }
    const float* bias = (const float*)(A+BIAS);

#pragma unroll 1
    for (int mtx = 0; mtx < 3; mtx++) {
        float acc[8][4];
#pragma unroll
        for (int ob = 0; ob < 8; ob++) {
            float b0 = bias[mtx*64 + ob*8 + (lane&3)*2];
            float b1 = bias[mtx*64 + ob*8 + (lane&3)*2 + 1];
            acc[ob][0]=b0; acc[ob][1]=b1; acc[ob][2]=b0; acc[ob][3]=b1;
        }
#pragma unroll
        for (int kk = 0; kk < 4; kk++) {
#pragma unroll
            for (int op = 0; op < 4; op++) {
                uint32_t off = swz((uint32_t)((op*16 + ((lane>>4)&1)*8 + (lane&7))*128
                                              + kk*32 + ((lane>>3)&1)*16));
                uint32_t bw[4];
                ldsm4(bw, Au + mtx*8192u + off);
                mma_f16(acc[2*op],   ax[kk], &bw[0]);
                mma_f16(acc[2*op+1], ax[kk], &bw[2]);
            }
        }
        __syncthreads();
#pragma unroll
        for (int ob = 0; ob < 8; ob++) {
            int o = ob*8 + (lane&3)*2, r = lane>>2;
            *(uint32_t*)(A + STG + swz((uint32_t)((m0+r)*128   + o*2))) = cvtpack(acc[ob][0], acc[ob][1]);
            *(uint32_t*)(A + STG + swz((uint32_t)((m0+r+8)*128 + o*2))) = cvtpack(acc[ob][2], acc[ob][3]);
        }
        __syncthreads();
        if (mtx < 2) {
            __half* dst = ((mtx==0)?g_fq:g_gq) + ((size_t)b*NPIX + n0)*CH;
            int n = t>>1, half = t&1;
#pragma unroll
            for (int q16 = 0; q16 < 4; q16++) {
                int4 v = *(int4*)(A + STG + swz((uint32_t)(n*128 + half*64 + q16*16)));
                *(int4*)((char*)(dst + (size_t)n*CH + half*32) + q16*16) = v;
            }
        } else {
            int c = t>>2, sg = t&3;
            __half* dst = g_hq + ((size_t)b*CH + c)*NPIX + n0 + sg*32;
#pragma unroll
            for (int u = 0; u < 16; u++) {
                int n = sg*32 + 2*u;
                uint32_t e0 = *(uint16_t*)(A + STG + swz((uint32_t)(n*128 + c*2)));
                uint32_t e1 = *(uint16_t*)(A + STG + swz((uint32_t)((n+1)*128 + c*2)));
                *(uint32_t*)(dst + 2*u) = e0 | (e1<<16);
            }
        }
    }
}

// ---------------- Pass 1: L[i]; 4 warps x 32 i, i-tile 128 -------------------
// grid (32, 8), 128 threads. smem: F 16K | G dbl 2x16K = 48K. 2 CTAs/SM.
__global__ __launch_bounds__(128,2) void pass1_hmma()
{
    extern __shared__ uint8_t dyn1[];
    uint8_t* A = (uint8_t*)(((uintptr_t)dyn1 + 1023) & ~(uintptr_t)1023);
    const uint32_t Au = smem_u32(A);
    const uint32_t FQ=0, GB=16384;

    const int t = threadIdx.x, lane = t&31, wid = t>>5;
    const int b = blockIdx.y, i0 = blockIdx.x*128;

    {
        const char* fq = (const char*)(g_fq + ((size_t)b*NPIX+i0)*CH);
        for (int q = t; q < 1024; q += 128) CP16(Au+FQ+swz(q*16), fq + q*16);
        CPCOMMIT();
    }
#pragma unroll 1
    for (int pre = 0; pre < 2; pre++) {
        const char* gq = (const char*)(g_gq + ((size_t)b*NPIX + pre*128)*CH);
        uint32_t base = Au + GB + pre*16384;
        for (int q = t; q < 1024; q += 128) CP16(base+swz(q*16), gq + q*16);
        CPCOMMIT();
    }
    CPWAIT(2); __syncthreads();

    uint32_t af[2][4][4];
#pragma unroll
    for (int s = 0; s < 2; s++)
#pragma unroll
    for (int kk = 0; kk < 4; kk++) {
        uint32_t off = swz((uint32_t)((wid*32 + s*16 + (lane&15))*128 + kk*32 + ((lane>>4)&1)*16));
        ldsm4(af[s][kk], Au+FQ+off);
    }

    float z[2][2] = {{0.f,0.f},{0.f,0.f}};

#pragma unroll 1
    for (int jt = 0; jt < 32; jt++) {
        CPWAIT(1); __syncthreads();
        uint32_t gb = Au + GB + (uint32_t)(jt&1)*16384;

        uint32_t sacc[2][16][2];
#pragma unroll
        for (int s = 0; s < 2; s++)
#pragma unroll
        for (int nb = 0; nb < 16; nb++) { sacc[s][nb][0]=0u; sacc[s][nb][1]=0u; }

#pragma unroll
        for (int kk = 0; kk < 4; kk++) {
#pragma unroll
            for (int p = 0; p < 8; p++) {
                uint32_t off = swz((uint32_t)((p*16 + ((lane>>4)&1)*8 + (lane&7))*128
                                              + kk*32 + ((lane>>3)&1)*16));
                uint32_t bh[4];
                ldsm4(bh, gb+off);
                mma_h16(sacc[0][2*p],   af[0][kk], &bh[0]);
                mma_h16(sacc[0][2*p+1], af[0][kk], &bh[2]);
                mma_h16(sacc[1][2*p],   af[1][kk], &bh[0]);
                mma_h16(sacc[1][2*p+1], af[1][kk], &bh[2]);
            }
        }
#pragma unroll
        for (int s = 0; s < 2; s++)
#pragma unroll
        for (int nb = 0; nb < 16; nb++) {
            float2 a = __half22float2(*(const __half2*)&sacc[s][nb][0]);
            float2 c = __half22float2(*(const __half2*)&sacc[s][nb][1]);
            z[s][0] += ex2(a.x) + ex2(a.y);
            z[s][1] += ex2(c.x) + ex2(c.y);
        }

        __syncthreads();
        if (jt+2 < 32) {
            const char* gq = (const char*)(g_gq + ((size_t)b*NPIX + (jt+2)*128)*CH);
            uint32_t base = Au + GB + (uint32_t)(jt&1)*16384;
            for (int q = t; q < 1024; q += 128) CP16(base+swz(q*16), gq + q*16);
        }
        CPCOMMIT();
    }

#pragma unroll
    for (int s = 0; s < 2; s++) {
        float z0 = z[s][0], z1 = z[s][1];
        z0 += __shfl_xor_sync(0xFFFFFFFFu, z0, 1);
        z0 += __shfl_xor_sync(0xFFFFFFFFu, z0, 2);
        z1 += __shfl_xor_sync(0xFFFFFFFFu, z1, 1);
        z1 += __shfl_xor_sync(0xFFFFFFFFu, z1, 2);
        if ((lane&3) == 0) {
            int r = b*NPIX + i0 + wid*32 + s*16 + (lane>>2);
            g_L[r]   = lg2(z0);
            g_L[r+8] = lg2(z1);
        }
    }
}

// ---------------- Pass 2: out'[j,c]; 4 warps x 32 j, j-tile 128 ---------------
// grid (32, 8), 128 threads. smem: G 16K + 2 x 16.25K. 2 CTAs/SM.
#define BUFST 16640u
#define B0    16384u
#define OF_FQ 0u
#define OF_HH 8192u
#define OF_L  16384u
__global__ __launch_bounds__(128,2) void pass2_hmma(
    const float* __restrict__ x, const float* __restrict__ gamma,
    float* __restrict__ out)
{
    extern __shared__ uint8_t dyn2[];
    uint8_t* A = (uint8_t*)(((uintptr_t)dyn2 + 1023) & ~(uintptr_t)1023);
    const uint32_t Au = smem_u32(A);

    const int t = threadIdx.x, lane = t&31, wid = t>>5;
    const int b = blockIdx.y, j0 = blockIdx.x*128;

    {
        const char* gq = (const char*)(g_gq + ((size_t)b*NPIX+j0)*CH);
        for (int q = t; q < 1024; q += 128) CP16(Au+swz(q*16), gq + q*16);
        CPCOMMIT();
    }
#pragma unroll 1
    for (int pre = 0; pre < 2; pre++) {
        const int i0 = pre*64;
        uint32_t base = Au + B0 + pre*BUFST;
        const char* fq = (const char*)(g_fq + ((size_t)b*NPIX+i0)*CH);
        for (int q = t; q < 512; q += 128) CP16(base+OF_FQ+swz(q*16), fq + q*16);
        const char* hq = (const char*)(g_hq + (size_t)b*CH*NPIX + i0);
        for (int q = t; q < 512; q += 128)
            CP16(base+OF_HH+swz(q*16), hq + (uint32_t)(q>>3)*NPIX*2 + (uint32_t)(q&7)*16);
        if (t < 16) CP16(base+OF_L + t*16, (const char*)(g_L + b*NPIX + i0) + t*16);
        CPCOMMIT();
    }
    CPWAIT(2); __syncthreads();

    uint32_t ag[2][4][4];
#pragma unroll
    for (int s = 0; s < 2; s++)
#pragma unroll
    for (int kk = 0; kk < 4; kk++) {
        uint32_t off = swz((uint32_t)((wid*32 + s*16 + (lane&15))*128 + kk*32 + ((lane>>4)&1)*16));
        ldsm4(ag[s][kk], Au+off);
    }

    float oacc[2][8][4];
#pragma unroll
    for (int s = 0; s < 2; s++)
#pragma unroll
    for (int nb = 0; nb < 8; nb++) { oacc[s][nb][0]=0.f; oacc[s][nb][1]=0.f; oacc[s][nb][2]=0.f; oacc[s][nb][3]=0.f; }

#pragma unroll 1
    for (int it = 0; it < 64; it++) {
        CPWAIT(1); __syncthreads();
        uint32_t bb = Au + B0 + (uint32_t)(it&1)*BUFST;
        const float* Lf = (const float*)(A + B0 + (it&1)*BUFST + OF_L);

        uint32_t L2[8];
#pragma unroll
        for (int nb = 0; nb < 8; nb++) {
            int ic = nb*8 + (lane&3)*2;
            L2[nb] = cvtpack(Lf[ic], Lf[ic+1]);
        }

        uint32_t sacc[2][8][2];
#pragma unroll
        for (int s = 0; s < 2; s++)
#pragma unroll
        for (int nb = 0; nb < 8; nb++) { sacc[s][nb][0]=0u; sacc[s][nb][1]=0u; }
#pragma unroll
        for (int kk = 0; kk < 4; kk++) {
#pragma unroll
            for (int p = 0; p < 4; p++) {
                uint32_t off = swz((uint32_t)((p*16 + ((lane>>4)&1)*8 + (lane&7))*128
                                              + kk*32 + ((lane>>3)&1)*16));
                uint32_t bh[4];
                ldsm4(bh, bb+OF_FQ+off);
                mma_h16(sacc[0][2*p],   ag[0][kk], &bh[0]);
                mma_h16(sacc[0][2*p+1], ag[0][kk], &bh[2]);
                mma_h16(sacc[1][2*p],   ag[1][kk], &bh[0]);
                mma_h16(sacc[1][2*p+1], ag[1][kk], &bh[2]);
            }
        }

#pragma unroll
        for (int kk2 = 0; kk2 < 4; kk2++) {
            int nb0 = 2*kk2, nb1 = nb0+1;
            uint32_t aH0[4], aH1[4];
            aH0[0] = ex2h2(sub2(sacc[0][nb0][0], L2[nb0]));
            aH0[1] = ex2h2(sub2(sacc[0][nb0][1], L2[nb0]));
            aH0[2] = ex2h2(sub2(sacc[0][nb1][0], L2[nb1]));
            aH0[3] = ex2h2(sub2(sacc[0][nb1][1], L2[nb1]));
            aH1[0] = ex2h2(sub2(sacc[1][nb0][0], L2[nb0]));
            aH1[1] = ex2h2(sub2(sacc[1][nb0][1], L2[nb0]));
            aH1[2] = ex2h2(sub2(sacc[1][nb1][0], L2[nb1]));
            aH1[3] = ex2h2(sub2(sacc[1][nb1][1], L2[nb1]));
#pragma unroll
            for (int p = 0; p < 4; p++) {
                uint32_t off = swz((uint32_t)((p*16 + ((lane>>4)&1)*8 + (lane&7))*128
                                              + kk2*32 + ((lane>>3)&1)*16));
                uint32_t bh[4];
                ldsm4(bh, bb+OF_HH+off);
                mma_f16(oacc[0][2*p],   aH0, &bh[0]);
                mma_f16(oacc[0][2*p+1], aH0, &bh[2]);
                mma_f16(oacc[1][2*p],   aH1, &bh[0]);
                mma_f16(oacc[1][2*p+1], aH1, &bh[2]);
            }
        }

        __syncthreads();
        if (it+2 < 64) {
            const int i0 = (it+2)*64;
            uint32_t base = Au + B0 + (uint32_t)(it&1)*BUFST;
            const char* fq = (const char*)(g_fq + ((size_t)b*NPIX+i0)*CH);
            for (int q = t; q < 512; q += 128) CP16(base+OF_FQ+swz(q*16), fq + q*16);
            const char* hq = (const char*)(g_hq + (size_t)b*CH*NPIX + i0);
            for (int q = t; q < 512; q += 128)
                CP16(base+OF_HH+swz(q*16), hq + (uint32_t)(q>>3)*NPIX*2 + (uint32_t)(q&7)*16);
            if (t < 16) CP16(base+OF_L + t*16, (const char*)(g_L + b*NPIX + i0) + t*16);
        }
        CPCOMMIT();
    }

    // Epilogue: stage [64 c][128 j] fp32 (reuses smem), coalesced gamma*o + x
    CPWAIT(0); __syncthreads();
    float* outs = (float*)A;
#pragma unroll
    for (int s = 0; s < 2; s++) {
        const int jl = wid*32 + s*16 + (lane>>2);
#pragma unroll
        for (int nb = 0; nb < 8; nb++) {
            int c0 = nb*8 + (lane&3)*2;
            outs[c0*128 + jl]         = oacc[s][nb][0];
            outs[(c0+1)*128 + jl]     = oacc[s][nb][1];
            outs[c0*128 + jl + 8]     = oacc[s][nb][2];
            outs[(c0+1)*128 + jl + 8] = oacc[s][nb][3];
        }
    }
    __syncthreads();
    const float gam = *gamma;
    {
        const int row = t>>1, seg = t&1;   // row = channel, seg covers 64 j
        const float* xr   = x   + ((size_t)b*CH + row)*NPIX + j0 + seg*64;
        float*       orow = out + ((size_t)b*CH + row)*NPIX + j0 + seg*64;
        const float4* sr = (const float4*)(outs + row*128 + seg*64);
#pragma unroll
        for (int u = 0; u < 16; u++) {
            float4 v = sr[u];
            float4 xv = *(const float4*)(xr + u*4);
            float4 r;
            r.x = gam*v.x + xv.x; r.y = gam*v.y + xv.y;
            r.z = gam*v.z + xv.z; r.w = gam*v.w + xv.w;
            *(float4*)(orow + u*4) = r;
        }
    }
}

// -----------------------------------------------------------------------------
extern "C" void kernel_launch(void* const* d_in, const int* in_sizes, int n_in,
                              void* d_out, int out_size)
{
    const float* x     = (const float*)d_in[0];
    const float* Wf    = (const float*)d_in[1];
    const float* bf    = (const float*)d_in[2];
    const float* Wg    = (const float*)d_in[3];
    const float* bg    = (const float*)d_in[4];
    const float* Wh    = (const float*)d_in[5];
    const float* bh    = (const float*)d_in[6];
    const float* gamma = (const float*)d_in[7];
    float* out = (float*)d_out;
    (void)in_sizes; (void)n_in; (void)out_size;

    cudaFuncSetAttribute(fgh_hmma,   cudaFuncAttributeMaxDynamicSharedMemorySize, 58368+1024);
    cudaFuncSetAttribute(pass1_hmma, cudaFuncAttributeMaxDynamicSharedMemorySize, 49152+1024);
    cudaFuncSetAttribute(pass2_hmma, cudaFuncAttributeMaxDynamicSharedMemorySize, 49664+1024);

    prep_w<<<1, 256>>>(Wf, bf, Wg, bg, Wh, bh);
    fgh_hmma<<<dim3(32, BATCH), 256, 58368+1024>>>(x);
    pass1_hmma<<<dim3(32, BATCH), 128, 49152+1024>>>();
    pass2_hmma<<<dim3(32, BATCH), 128, 49664+1024>>>(x, gamma, out);
}

// round 11
// speedup vs baseline: 1.0740x; 1.0037x over previous
#include <cuda_runtime.h>
#include <cuda_fp16.h>
#include <cstdint>

#define BATCH 8
#define CH    64
#define NPIX  4096

__device__ __align__(128) __half g_fq[BATCH*NPIX*CH]; // f*log2e [b][n][c]
__device__ __align__(128) __half g_gq[BATCH*NPIX*CH]; // g       [b][n][c]
__device__ __align__(128) __half g_hq[BATCH*CH*NPIX]; // h       [b][c][n]
__device__ float g_L[BATCH*NPIX];
__device__ __align__(128) uint8_t g_Wq[24576];
__device__ __align__(128) float   g_bias[192];

__device__ __forceinline__ uint32_t smem_u32(const void* p){
    uint32_t a; asm("{ .reg .u64 t; cvta.to.shared.u64 t, %1; cvt.u32.u64 %0, t; }":"=r"(a):"l"(p)); return a;
}
__device__ __forceinline__ uint32_t swz(uint32_t o){ return o ^ ((o>>3)&0x70); }
__device__ __forceinline__ uint32_t swzH(uint32_t o){ return o ^ ((o>>4)&0x70); }
__device__ __forceinline__ float ex2(float x){
    float y; asm("ex2.approx.f32 %0, %1;":"=f"(y):"f"(x)); return y;
}
__device__ __forceinline__ float lg2(float x){
    float y; asm("lg2.approx.f32 %0, %1;":"=f"(y):"f"(x)); return y;
}
__device__ __forceinline__ uint32_t cvtpack(float lo, float hi){
    uint32_t r; asm("cvt.rn.f16x2.f32 %0, %1, %2;" : "=r"(r) : "f"(hi), "f"(lo)); return r;
}
__device__ __forceinline__ uint32_t sub2(uint32_t a, uint32_t b){
    uint32_t r; asm("sub.rn.f16x2 %0, %1, %2;" : "=r"(r) : "r"(a), "r"(b)); return r;
}
__device__ __forceinline__ uint32_t ex2h2(uint32_t a){
    uint32_t r; asm("ex2.approx.f16x2 %0, %1;" : "=r"(r) : "r"(a)); return r;
}
#define CP16(dst, src) asm volatile("cp.async.cg.shared.global [%0], [%1], 16;"::"r"(dst),"l"(src):"memory")
#define CPCOMMIT()     asm volatile("cp.async.commit_group;":::"memory")
#define CPWAIT(n)      asm volatile("cp.async.wait_group %0;"::"n"(n):"memory")

__device__ __forceinline__ void ldsm4(uint32_t r[4], uint32_t addr){
    asm volatile("ldmatrix.sync.aligned.m8n8.x4.shared.b16 {%0,%1,%2,%3},[%4];"
        : "=r"(r[0]),"=r"(r[1]),"=r"(r[2]),"=r"(r[3]) : "r"(addr));
}
__device__ __forceinline__ void ldsm4t(uint32_t r[4], uint32_t addr){
    asm volatile("ldmatrix.sync.aligned.m8n8.x4.trans.shared.b16 {%0,%1,%2,%3},[%4];"
        : "=r"(r[0]),"=r"(r[1]),"=r"(r[2]),"=r"(r[3]) : "r"(addr));
}
__device__ __forceinline__ void mma_f16(float d[4], const uint32_t a[4], const uint32_t b[2]){
    asm volatile("mma.sync.aligned.m16n8k16.row.col.f32.f16.f16.f32 "
        "{%0,%1,%2,%3},{%4,%5,%6,%7},{%8,%9},{%0,%1,%2,%3};"
        : "+f"(d[0]),"+f"(d[1]),"+f"(d[2]),"+f"(d[3])
        : "r"(a[0]),"r"(a[1]),"r"(a[2]),"r"(a[3]),"r"(b[0]),"r"(b[1]));
}
__device__ __forceinline__ void mma_h16(uint32_t d[2], const uint32_t a[4], const uint32_t b[2]){
    asm volatile("mma.sync.aligned.m16n8k16.row.col.f16.f16.f16.f16 "
        "{%0,%1},{%2,%3,%4,%5},{%6,%7},{%0,%1};"
        : "+r"(d[0]),"+r"(d[1])
        : "r"(a[0]),"r"(a[1]),"r"(a[2]),"r"(a[3]),"r"(b[0]),"r"(b[1]));
}

// ---------------- Stage 0: W/bias prep ---------------------------------------
__global__ __launch_bounds__(256) void prep_w(
    const float* __restrict__ Wf, const float* __restrict__ bf,
    const float* __restrict__ Wg, const float* __restrict__ bg,
    const float* __restrict__ Wh, const float* __restrict__ bh)
{
    const int t = threadIdx.x;
    for (int q = t; q < 3*4096; q += 256) {
        int mtx = q >> 12, idx = q & 4095;
        const float* Wsrc = (mtx==0)?Wf:((mtx==1)?Wg:Wh);
        float v = Wsrc[idx] * ((mtx==0) ? 1.44269504f : 1.0f);
        int o = idx >> 6, k = idx & 63;
        *(__half*)(g_Wq + mtx*8192u + swz(o*128 + k*2)) = __float2half_rn(v);
    }
    if (t < 192) {
        const float* bsrc = (t<64)?bf:((t<128)?bg:bh);
        g_bias[t] = bsrc[t&63] * ((t<64) ? 1.44269504f : 1.0f);
    }
}

// ---------------- Stage A: projections via HMMA ------------------------------
__global__ __launch_bounds__(256,2) void fgh_hmma(const float* __restrict__ x)
{
    extern __shared__ uint8_t dyn0[];
    uint8_t* A = (uint8_t*)(((uintptr_t)dyn0 + 1023) & ~(uintptr_t)1023);
    const uint32_t Au = smem_u32(A);
    const uint32_t BIAS=24576, SX=25600, STG=41984;

    const int t = threadIdx.x, lane = t&31, wid = t>>5;
    const int b = blockIdx.y, n0 = blockIdx.x*128;

    for (int q = t; q < 1536; q += 256) CP16(Au + q*16, (const char*)g_Wq + q*16);
    if (t < 48) CP16(Au + BIAS + t*16, (const char*)g_bias + t*16);
    CPCOMMIT();

    {
        int c = t>>2, nb0 = (t&3)*32;
        const float* xr = x + ((size_t)b*CH + c)*NPIX + n0 + nb0;
        for (int u = 0; u < 16; u++) {
            float2 v = *(const float2*)(xr + 2*u);
            *(uint32_t*)(A + SX + swzH((uint32_t)(c*256 + (nb0+2*u)*2))) = cvtpack(v.x, v.y);
        }
    }
    CPWAIT(0); __syncthreads();

    uint32_t ax[4][4];
    const int m0 = wid*16;
#pragma unroll
    for (int kk = 0; kk < 4; kk++) {
        int row = kk*16 + (lane&7) + ((lane>>4)<<3);
        int col = m0 + ((lane>>3)&1)*8;
        ldsm4t(ax[kk], Au + SX + swzH((uint32_t)(row*256 + col*2)));
    }
    const float* bias = (const float*)(A+BIAS);

#pragma unroll 1
    for (int mtx = 0; mtx < 3; mtx++) {
        float acc[8][4];
#pragma unroll
        for (int ob = 0; ob < 8; ob++) {
            float b0 = bias[mtx*64 + ob*8 + (lane&3)*2];
            float b1 = bias[mtx*64 + ob*8 + (lane&3)*2 + 1];
            acc[ob][0]=b0; acc[ob][1]=b1; acc[ob][2]=b0; acc[ob][3]=b1;
        }
#pragma unroll
        for (int kk = 0; kk < 4; kk++) {
#pragma unroll
            for (int op = 0; op < 4; op++) {
                uint32_t off = swz((uint32_t)((op*16 + ((lane>>4)&1)*8 + (lane&7))*128
                                              + kk*32 + ((lane>>3)&1)*16));
                uint32_t bw[4];
                ldsm4(bw, Au + mtx*8192u + off);
                mma_f16(acc[2*op],   ax[kk], &bw[0]);
                mma_f16(acc[2*op+1], ax[kk], &bw[2]);
            }
        }
        __syncthreads();
#pragma unroll
        for (int ob = 0; ob < 8; ob++) {
            int o = ob*8 + (lane&3)*2, r = lane>>2;
            *(uint32_t*)(A + STG + swz((uint32_t)((m0+r)*128   + o*2))) = cvtpack(acc[ob][0], acc[ob][1]);
            *(uint32_t*)(A + STG + swz((uint32_t)((m0+r+8)*128 + o*2))) = cvtpack(acc[ob][2], acc[ob][3]);
        }
        __syncthreads();
        if (mtx < 2) {
            __half* dst = ((mtx==0)?g_fq:g_gq) + ((size_t)b*NPIX + n0)*CH;
            int n = t>>1, half = t&1;
#pragma unroll
            for (int q16 = 0; q16 < 4; q16++) {
                int4 v = *(int4*)(A + STG + swz((uint32_t)(n*128 + half*64 + q16*16)));
                *(int4*)((char*)(dst + (size_t)n*CH + half*32) + q16*16) = v;
            }
        } else {
            int c = t>>2, sg = t&3;
            __half* dst = g_hq + ((size_t)b*CH + c)*NPIX + n0 + sg*32;
#pragma unroll
            for (int u = 0; u < 16; u++) {
                int n = sg*32 + 2*u;
                uint32_t e0 = *(uint16_t*)(A + STG + swz((uint32_t)(n*128 + c*2)));
                uint32_t e1 = *(uint16_t*)(A + STG + swz((uint32_t)((n+1)*128 + c*2)));
                *(uint32_t*)(dst + 2*u) = e0 | (e1<<16);
            }
        }
    }
}

// ---------------- Pass 1: L[i]; 2 warps x 32 i, i-tile 64 --------------------
// grid (64, 8), 64 threads. smem: F 8K | G dbl 2x16K = 40K. ~3.5 CTAs/SM.
__global__ __launch_bounds__(64,4) void pass1_hmma()
{
    extern __shared__ uint8_t dyn1[];
    uint8_t* A = (uint8_t*)(((uintptr_t)dyn1 + 1023) & ~(uintptr_t)1023);
    const uint32_t Au = smem_u32(A);
    const uint32_t FQ=0, GB=8192;

    const int t = threadIdx.x, lane = t&31, wid = t>>5;
    const int b = blockIdx.y, i0 = blockIdx.x*64;

    {
        const char* fq = (const char*)(g_fq + ((size_t)b*NPIX+i0)*CH);
        for (int q = t; q < 512; q += 64) CP16(Au+FQ+swz(q*16), fq + q*16);
        CPCOMMIT();
    }
#pragma unroll 1
    for (int pre = 0; pre < 2; pre++) {
        const char* gq = (const char*)(g_gq + ((size_t)b*NPIX + pre*128)*CH);
        uint32_t base = Au + GB + pre*16384;
        for (int q = t; q < 1024; q += 64) CP16(base+swz(q*16), gq + q*16);
        CPCOMMIT();
    }
    CPWAIT(2); __syncthreads();

    uint32_t af[2][4][4];
#pragma unroll
    for (int s = 0; s < 2; s++)
#pragma unroll
    for (int kk = 0; kk < 4; kk++) {
        uint32_t off = swz((uint32_t)((wid*32 + s*16 + (lane&15))*128 + kk*32 + ((lane>>4)&1)*16));
        ldsm4(af[s][kk], Au+FQ+off);
    }

    float z[2][2] = {{0.f,0.f},{0.f,0.f}};

#pragma unroll 1
    for (int jt = 0; jt < 32; jt++) {
        CPWAIT(1); __syncthreads();
        uint32_t gb = Au + GB + (uint32_t)(jt&1)*16384;

        uint32_t sacc[2][16][2];
#pragma unroll
        for (int s = 0; s < 2; s++)
#pragma unroll
        for (int nb = 0; nb < 16; nb++) { sacc[s][nb][0]=0u; sacc[s][nb][1]=0u; }

#pragma unroll
        for (int kk = 0; kk < 4; kk++) {
#pragma unroll
            for (int p = 0; p < 8; p++) {
                uint32_t off = swz((uint32_t)((p*16 + ((lane>>4)&1)*8 + (lane&7))*128
                                              + kk*32 + ((lane>>3)&1)*16));
                uint32_t bh[4];
                ldsm4(bh, gb+off);
                mma_h16(sacc[0][2*p],   af[0][kk], &bh[0]);
                mma_h16(sacc[0][2*p+1], af[0][kk], &bh[2]);
                mma_h16(sacc[1][2*p],   af[1][kk], &bh[0]);
                mma_h16(sacc[1][2*p+1], af[1][kk], &bh[2]);
            }
        }
#pragma unroll
        for (int s = 0; s < 2; s++)
#pragma unroll
        for (int nb = 0; nb < 16; nb++) {
            float2 a = __half22float2(*(const __half2*)&sacc[s][nb][0]);
            float2 c = __half22float2(*(const __half2*)&sacc[s][nb][1]);
            z[s][0] += ex2(a.x) + ex2(a.y);
            z[s][1] += ex2(c.x) + ex2(c.y);
        }

        __syncthreads();
        if (jt+2 < 32) {
            const char* gq = (const char*)(g_gq + ((size_t)b*NPIX + (jt+2)*128)*CH);
            uint32_t base = Au + GB + (uint32_t)(jt&1)*16384;
            for (int q = t; q < 1024; q += 64) CP16(base+swz(q*16), gq + q*16);
        }
        CPCOMMIT();
    }

#pragma unroll
    for (int s = 0; s < 2; s++) {
        float z0 = z[s][0], z1 = z[s][1];
        z0 += __shfl_xor_sync(0xFFFFFFFFu, z0, 1);
        z0 += __shfl_xor_sync(0xFFFFFFFFu, z0, 2);
        z1 += __shfl_xor_sync(0xFFFFFFFFu, z1, 1);
        z1 += __shfl_xor_sync(0xFFFFFFFFu, z1, 2);
        if ((lane&3) == 0) {
            int r = b*NPIX + i0 + wid*32 + s*16 + (lane>>2);
            g_L[r]   = lg2(z0);
            g_L[r+8] = lg2(z1);
        }
    }
}

// ---------------- Pass 2: out'[j,c]; 2 warps x 32 j, j-tile 64 ----------------
// grid (64, 8), 64 threads. smem: G 8K + 2 x 16.25K = 41.5K. ~3.5 CTAs/SM.
#define BUFST 16640u
#define B0    8192u
#define OF_FQ 0u
#define OF_HH 8192u
#define OF_L  16384u
__global__ __launch_bounds__(64,4) void pass2_hmma(
    const float* __restrict__ x, const float* __restrict__ gamma,
    float* __restrict__ out)
{
    extern __shared__ uint8_t dyn2[];
    uint8_t* A = (uint8_t*)(((uintptr_t)dyn2 + 1023) & ~(uintptr_t)1023);
    const uint32_t Au = smem_u32(A);

    const int t = threadIdx.x, lane = t&31, wid = t>>5;
    const int b = blockIdx.y, j0 = blockIdx.x*64;

    {
        const char* gq = (const char*)(g_gq + ((size_t)b*NPIX+j0)*CH);
        for (int q = t; q < 512; q += 64) CP16(Au+swz(q*16), gq + q*16);
        CPCOMMIT();
    }
#pragma unroll 1
    for (int pre = 0; pre < 2; pre++) {
        const int i0 = pre*64;
        uint32_t base = Au + B0 + pre*BUFST;
        const char* fq = (const char*)(g_fq + ((size_t)b*NPIX+i0)*CH);
        for (int q = t; q < 512; q += 64) CP16(base+OF_FQ+swz(q*16), fq + q*16);
        const char* hq = (const char*)(g_hq + (size_t)b*CH*NPIX + i0);
        for (int q = t; q < 512; q += 64)
            CP16(base+OF_HH+swz(q*16), hq + (uint32_t)(q>>3)*NPIX*2 + (uint32_t)(q&7)*16);
        if (t < 16) CP16(base+OF_L + t*16, (const char*)(g_L + b*NPIX + i0) + t*16);
        CPCOMMIT();
    }
    CPWAIT(2); __syncthreads();

    uint32_t ag[2][4][4];
#pragma unroll
    for (int s = 0; s < 2; s++)
#pragma unroll
    for (int kk = 0; kk < 4; kk++) {
        uint32_t off = swz((uint32_t)((wid*32 + s*16 + (lane&15))*128 + kk*32 + ((lane>>4)&1)*16));
        ldsm4(ag[s][kk], Au+off);
    }

    float oacc[2][8][4];
#pragma unroll
    for (int s = 0; s < 2; s++)
#pragma unroll
    for (int nb = 0; nb < 8; nb++) { oacc[s][nb][0]=0.f; oacc[s][nb][1]=0.f; oacc[s][nb][2]=0.f; oacc[s][nb][3]=0.f; }

#pragma unroll 1
    for (int it = 0; it < 64; it++) {
        CPWAIT(1); __syncthreads();
        uint32_t bb = Au + B0 + (uint32_t)(it&1)*BUFST;
        const float* Lf = (const float*)(A + B0 + (it&1)*BUFST + OF_L);

        uint32_t L2[8];
#pragma unroll
        for (int nb = 0; nb < 8; nb++) {
            int ic = nb*8 + (lane&3)*2;
            L2[nb] = cvtpack(Lf[ic], Lf[ic+1]);
        }

        uint32_t sacc[2][8][2];
#pragma unroll
        for (int s = 0; s < 2; s++)
#pragma unroll
        for (int nb = 0; nb < 8; nb++) { sacc[s][nb][0]=0u; sacc[s][nb][1]=0u; }
#pragma unroll
        for (int kk = 0; kk < 4; kk++) {
#pragma unroll
            for (int p = 0; p < 4; p++) {
                uint32_t off = swz((uint32_t)((p*16 + ((lane>>4)&1)*8 + (lane&7))*128
                                              + kk*32 + ((lane>>3)&1)*16));
                uint32_t bh[4];
                ldsm4(bh, bb+OF_FQ+off);
                mma_h16(sacc[0][2*p],   ag[0][kk], &bh[0]);
                mma_h16(sacc[0][2*p+1], ag[0][kk], &bh[2]);
                mma_h16(sacc[1][2*p],   ag[1][kk], &bh[0]);
                mma_h16(sacc[1][2*p+1], ag[1][kk], &bh[2]);
            }
        }

#pragma unroll
        for (int kk2 = 0; kk2 < 4; kk2++) {
            int nb0 = 2*kk2, nb1 = nb0+1;
            uint32_t aH0[4], aH1[4];
            aH0[0] = ex2h2(sub2(sacc[0][nb0][0], L2[nb0]));
            aH0[1] = ex2h2(sub2(sacc[0][nb0][1], L2[nb0]));
            aH0[2] = ex2h2(sub2(sacc[0][nb1][0], L2[nb1]));
            aH0[3] = ex2h2(sub2(sacc[0][nb1][1], L2[nb1]));
            aH1[0] = ex2h2(sub2(sacc[1][nb0][0], L2[nb0]));
            aH1[1] = ex2h2(sub2(sacc[1][nb0][1], L2[nb0]));
            aH1[2] = ex2h2(sub2(sacc[1][nb1][0], L2[nb1]));
            aH1[3] = ex2h2(sub2(sacc[1][nb1][1], L2[nb1]));
#pragma unroll
            for (int p = 0; p < 4; p++) {
                uint32_t off = swz((uint32_t)((p*16 + ((lane>>4)&1)*8 + (lane&7))*128
                                              + kk2*32 + ((lane>>3)&1)*16));
                uint32_t bh[4];
                ldsm4(bh, bb+OF_HH+off);
                mma_f16(oacc[0][2*p],   aH0, &bh[0]);
                mma_f16(oacc[0][2*p+1], aH0, &bh[2]);
                mma_f16(oacc[1][2*p],   aH1, &bh[0]);
                mma_f16(oacc[1][2*p+1], aH1, &bh[2]);
            }
        }

        __syncthreads();
        if (it+2 < 64) {
            const int i0 = (it+2)*64;
            uint32_t base = Au + B0 + (uint32_t)(it&1)*BUFST;
            const char* fq = (const char*)(g_fq + ((size_t)b*NPIX+i0)*CH);
            for (int q = t; q < 512; q += 64) CP16(base+OF_FQ+swz(q*16), fq + q*16);
            const char* hq = (const char*)(g_hq + (size_t)b*CH*NPIX + i0);
            for (int q = t; q < 512; q += 64)
                CP16(base+OF_HH+swz(q*16), hq + (uint32_t)(q>>3)*NPIX*2 + (uint32_t)(q&7)*16);
            if (t < 16) CP16(base+OF_L + t*16, (const char*)(g_L + b*NPIX + i0) + t*16);
        }
        CPCOMMIT();
    }

    // Epilogue: stage [64 c][64 j] fp32 (reuses smem), coalesced gamma*o + x
    CPWAIT(0); __syncthreads();
    float* outs = (float*)A;
#pragma unroll
    for (int s = 0; s < 2; s++) {
        const int jl = wid*32 + s*16 + (lane>>2);
#pragma unroll
        for (int nb = 0; nb < 8; nb++) {
            int c0 = nb*8 + (lane&3)*2;
            outs[c0*64 + jl]         = oacc[s][nb][0];
            outs[(c0+1)*64 + jl]     = oacc[s][nb][1];
            outs[c0*64 + jl + 8]     = oacc[s][nb][2];
            outs[(c0+1)*64 + jl + 8] = oacc[s][nb][3];
        }
    }
    __syncthreads();
    const float gam = *gamma;
    {
        const int row = t;   // channel
        const float* xr   = x   + ((size_t)b*CH + row)*NPIX + j0;
        float*       orow = out + ((size_t)b*CH + row)*NPIX + j0;
        const float4* sr = (const float4*)(outs + row*64);
#pragma unroll
        for (int u = 0; u < 16; u++) {
            float4 v = sr[u];
            float4 xv = *(const float4*)(xr + u*4);
            float4 r;
            r.x = gam*v.x + xv.x; r.y = gam*v.y + xv.y;
            r.z = gam*v.z + xv.z; r.w = gam*v.w + xv.w;
            *(float4*)(orow + u*4) = r;
        }
    }
}

// -----------------------------------------------------------------------------
extern "C" void kernel_launch(void* const* d_in, const int* in_sizes, int n_in,
                              void* d_out, int out_size)
{
    const float* x     = (const float*)d_in[0];
    const float* Wf    = (const float*)d_in[1];
    const float* bf    = (const float*)d_in[2];
    const float* Wg    = (const float*)d_in[3];
    const float* bg    = (const float*)d_in[4];
    const float* Wh    = (const float*)d_in[5];
    const float* bh    = (const float*)d_in[6];
    const float* gamma = (const float*)d_in[7];
    float* out = (float*)d_out;
    (void)in_sizes; (void)n_in; (void)out_size;

    cudaFuncSetAttribute(fgh_hmma,   cudaFuncAttributeMaxDynamicSharedMemorySize, 58368+1024);
    cudaFuncSetAttribute(pass1_hmma, cudaFuncAttributeMaxDynamicSharedMemorySize, 40960+1024);
    cudaFuncSetAttribute(pass2_hmma, cudaFuncAttributeMaxDynamicSharedMemorySize, 41472+1024);

    prep_w<<<1, 256>>>(Wf, bf, Wg, bg, Wh, bh);
    fgh_hmma<<<dim3(32, BATCH), 256, 58368+1024>>>(x);
    pass1_hmma<<<dim3(64, BATCH), 64, 40960+1024>>>();
    pass2_hmma<<<dim3(64, BATCH), 64, 41472+1024>>>(x, gamma, out);
}